// round 14
// baseline (speedup 1.0000x reference)
#include <cuda_runtime.h>

#define BATCH 512
#define NN    4096
#define KK    256
#define EPSF  0.1f
#define MUF   (1.0f / 4096.0f)
#define KF    256.0f
#define L2E   1.4426950408889634f
#define LN2   0.6931471805599453f

#define TPB   256
#define NG    4                  // float4 quad-groups per thread (16 elems)

__device__ float g_pmax[BATCH];

__device__ __forceinline__ float frcp(float x) {
    float y; asm("rcp.approx.ftz.f32 %0, %1;" : "=f"(y) : "f"(x)); return y;
}
__device__ __forceinline__ float fex2(float x) {
    float y; asm("ex2.approx.ftz.f32 %0, %1;" : "=f"(y) : "f"(x)); return y;
}

// Per-row max of C = max(s^2, (s-1)^2). PDL primary: signals dependents at top.
// Side effect: pulls the whole scores tensor through L2 (stays resident).
__global__ void __launch_bounds__(TPB)
max_kernel(const float* __restrict__ scores) {
    asm volatile("griddepcontrol.launch_dependents;" ::: "memory");
    const int b = blockIdx.x;
    const int t = threadIdx.x;
    const float4* s4 = (const float4*)(scores + b * NN);
    float m = 0.0f;
#pragma unroll
    for (int g = 0; g < NG; g++) {
        float4 s = s4[g * TPB + t];
        float a0 = s.x - 1.0f, a1 = s.y - 1.0f, a2 = s.z - 1.0f, a3 = s.w - 1.0f;
        m = fmaxf(m, fmaxf(fmaxf(s.x * s.x, a0 * a0), fmaxf(s.y * s.y, a1 * a1)));
        m = fmaxf(m, fmaxf(fmaxf(s.z * s.z, a2 * a2), fmaxf(s.w * s.w, a3 * a3)));
    }
#pragma unroll
    for (int o = 16; o > 0; o >>= 1)
        m = fmaxf(m, __shfl_xor_sync(0xFFFFFFFFu, m, o));
    __shared__ float red[8];
    if ((t & 31) == 0) red[t >> 5] = m;
    __syncthreads();
    if (t < 32) {
        float x = red[t & 7];
        x = fmaxf(x, __shfl_xor_sync(0xFFFFFFFFu, x, 4));
        x = fmaxf(x, __shfl_xor_sync(0xFFFFFFFFu, x, 2));
        x = fmaxf(x, __shfl_xor_sync(0xFFFFFFFFu, x, 1));
        if (t == 0) g_pmax[b] = x;
    }
}

// One block per row. Solve T(w) = sum_n 1/(1 + w r_n) = K.
// Waits FIRST, then loads scores L2-hot (max_kernel warmed them; no DRAM race).
// Guess: exact block moments of s. Rounds: Newton, Newton, Halley.
// Epilogue: first-order update of round-3 reciprocals (no recompute, no rcp).
__global__ void __launch_bounds__(TPB, 4)
sinkhorn_kernel(const float* __restrict__ scores, float* __restrict__ out) {
    const int b = blockIdx.x;
    const int t = threadIdx.x;
    const int wrp = t >> 5;
    const int lane = t & 31;

    __shared__ float cmaxsh;
    __shared__ __align__(16) float2 msum[8];      // per-warp (sum s, sum s^2)
    __shared__ __align__(16) float2 redN[2][8];   // Newton rounds: (S1,S2)
    __shared__ __align__(16) float4 redH[8];      // Halley round: (S1,S2,S3,-)

    asm volatile("griddepcontrol.wait;" ::: "memory");

    // ---- L2-hot score loads ----
    const float4* s4 = (const float4*)(scores + b * NN);
    float4 s[NG];
#pragma unroll
    for (int g = 0; g < NG; g++) s[g] = s4[g * TPB + t];

    // ---- cmax: warp 0 alone reduces the 512 row maxes (concurrent w/ loads) ----
    if (wrp == 0) {
        const float4* p4 = (const float4*)g_pmax;   // 128 float4
        float4 a = p4[lane];
        float4 c = p4[lane + 32];
        float4 d = p4[lane + 64];
        float4 e = p4[lane + 96];
        float m = fmaxf(fmaxf(fmaxf(a.x, a.y), fmaxf(a.z, a.w)),
                        fmaxf(fmaxf(c.x, c.y), fmaxf(c.z, c.w)));
        m = fmaxf(m, fmaxf(fmaxf(fmaxf(d.x, d.y), fmaxf(d.z, d.w)),
                           fmaxf(fmaxf(e.x, e.y), fmaxf(e.z, e.w))));
#pragma unroll
        for (int o = 16; o > 0; o >>= 1)
            m = fmaxf(m, __shfl_xor_sync(0xFFFFFFFFu, m, o));
        if (lane == 0) cmaxsh = m;
    }

    // ---- s-moments for the initial guess ----
    float ss = 0.0f, ss2 = 0.0f;
#pragma unroll
    for (int g = 0; g < NG; g++) {
        ss += (s[g].x + s[g].y) + (s[g].z + s[g].w);
        ss2 = fmaf(s[g].x, s[g].x, fmaf(s[g].y, s[g].y,
              fmaf(s[g].z, s[g].z, fmaf(s[g].w, s[g].w, ss2))));
    }
#pragma unroll
    for (int o = 16; o > 0; o >>= 1) {
        ss  += __shfl_xor_sync(0xFFFFFFFFu, ss, o);
        ss2 += __shfl_xor_sync(0xFFFFFFFFu, ss2, o);
    }
    if (lane == 0) msum[wrp] = make_float2(ss, ss2);
    __syncthreads();
    // cmax consumed -> allow next replay's max_kernel (rewrites identical values).
    asm volatile("griddepcontrol.launch_dependents;" ::: "memory");

    const float inv = frcp(cmaxsh * EPSF);     // 1/(cmax*eps)
    const float ca = 2.0f * inv * L2E;         // r = ex2(ca*s + cb)
    const float cb = -inv * L2E;

    // ---- exact-moment lognormal guess (ln r = (2s-1)*inv, affine in s) ----
    float w;
    {
        float2 a0 = msum[0], a1 = msum[1], a2 = msum[2], a3 = msum[3];
        float2 a4 = msum[4], a5 = msum[5], a6 = msum[6], a7 = msum[7];
        float S  = ((a0.x + a1.x) + (a2.x + a3.x)) + ((a4.x + a5.x) + (a6.x + a7.x));
        float Q  = ((a0.y + a1.y) + (a2.y + a3.y)) + ((a4.y + a5.y) + (a6.y + a7.y));
        float ms = S * MUF;                         // mean(s)
        float vs = fmaxf(Q * MUF - ms * ms, 0.0f);  // var(s)
        float mu_lnr = (2.0f * ms - 1.0f) * inv;
        float sg_lnr = 2.0f * sqrtf(vs) * inv;
        w = fex2((-mu_lnr - 1.53412f * sg_lnr) * L2E);
    }

    // ---- r in registers ----
    float r[4 * NG];
#pragma unroll
    for (int g = 0; g < NG; g++) {
        r[4 * g + 0] = fex2(fmaf(ca, s[g].x, cb));
        r[4 * g + 1] = fex2(fmaf(ca, s[g].y, cb));
        r[4 * g + 2] = fex2(fmaf(ca, s[g].z, cb));
        r[4 * g + 3] = fex2(fmaf(ca, s[g].w, cb));
    }

    // ---- rounds 1-2: Newton with (S1,S2) payload ----
#pragma unroll
    for (int it = 0; it < 2; it++) {
        float S1 = 0.0f, S2 = 0.0f;
#pragma unroll
        for (int g = 0; g < NG; g++) {
            float d0 = fmaf(w, r[4 * g + 0], 1.0f);
            float d1 = fmaf(w, r[4 * g + 1], 1.0f);
            float d2 = fmaf(w, r[4 * g + 2], 1.0f);
            float d3 = fmaf(w, r[4 * g + 3], 1.0f);
            float d01 = d0 * d1, d23 = d2 * d3;
            float rp = frcp(d01 * d23);
            float i0 = d1 * d23 * rp;
            float i1 = d0 * d23 * rp;
            float i2 = d3 * d01 * rp;
            float i3 = d2 * d01 * rp;
            S1 += (i0 + i1) + (i2 + i3);
            S2 = fmaf(i0, i0, fmaf(i1, i1, fmaf(i2, i2, fmaf(i3, i3, S2))));
        }
#pragma unroll
        for (int o = 16; o > 0; o >>= 1) {
            S1 += __shfl_xor_sync(0xFFFFFFFFu, S1, o);
            S2 += __shfl_xor_sync(0xFFFFFFFFu, S2, o);
        }
        if (lane == 0) redN[it][wrp] = make_float2(S1, S2);
        __syncthreads();
        {
            float2 v0 = redN[it][0], v1 = redN[it][1], v2 = redN[it][2], v3 = redN[it][3];
            float2 v4 = redN[it][4], v5 = redN[it][5], v6 = redN[it][6], v7 = redN[it][7];
            S1 = ((v0.x + v1.x) + (v2.x + v3.x)) + ((v4.x + v5.x) + (v6.x + v7.x));
            S2 = ((v0.y + v1.y) + (v2.y + v3.y)) + ((v4.y + v5.y) + (v6.y + v7.y));
        }
        float f = S1 - KF;
        float aa = fmaxf(S1 - S2, 1e-6f);            // -f' in ln w
        float d = fminf(4.0f, fmaxf(-4.0f, f * frcp(aa)));
        w = w * fex2(d * L2E);
    }

    // ---- round 3: Halley with (S1,S2,S3); keep i in registers ----
    float i[4 * NG];
    float dfin;
    {
        float S1 = 0.0f, S2 = 0.0f, S3 = 0.0f;
#pragma unroll
        for (int g = 0; g < NG; g++) {
            float d0 = fmaf(w, r[4 * g + 0], 1.0f);
            float d1 = fmaf(w, r[4 * g + 1], 1.0f);
            float d2 = fmaf(w, r[4 * g + 2], 1.0f);
            float d3 = fmaf(w, r[4 * g + 3], 1.0f);
            float d01 = d0 * d1, d23 = d2 * d3;
            float rp = frcp(d01 * d23);
            float i0 = d1 * d23 * rp;
            float i1 = d0 * d23 * rp;
            float i2 = d3 * d01 * rp;
            float i3 = d2 * d01 * rp;
            i[4 * g + 0] = i0; i[4 * g + 1] = i1;
            i[4 * g + 2] = i2; i[4 * g + 3] = i3;
            S1 += (i0 + i1) + (i2 + i3);
            float q0 = i0 * i0, q1 = i1 * i1, q2 = i2 * i2, q3 = i3 * i3;
            S2 += (q0 + q1) + (q2 + q3);
            S3 = fmaf(q0, i0, fmaf(q1, i1, fmaf(q2, i2, fmaf(q3, i3, S3))));
        }
#pragma unroll
        for (int o = 16; o > 0; o >>= 1) {
            S1 += __shfl_xor_sync(0xFFFFFFFFu, S1, o);
            S2 += __shfl_xor_sync(0xFFFFFFFFu, S2, o);
            S3 += __shfl_xor_sync(0xFFFFFFFFu, S3, o);
        }
        if (lane == 0) redH[wrp] = make_float4(S1, S2, S3, 0.0f);
        __syncthreads();
        {
            float4 v0 = redH[0], v1 = redH[1], v2 = redH[2], v3 = redH[3];
            float4 v4 = redH[4], v5 = redH[5], v6 = redH[6], v7 = redH[7];
            S1 = ((v0.x + v1.x) + (v2.x + v3.x)) + ((v4.x + v5.x) + (v6.x + v7.x));
            S2 = ((v0.y + v1.y) + (v2.y + v3.y)) + ((v4.y + v5.y) + (v6.y + v7.y));
            S3 = ((v0.z + v1.z) + (v2.z + v3.z)) + ((v4.z + v5.z) + (v6.z + v7.z));
        }
        float f = S1 - KF;
        float aa = fmaxf(S1 - S2, 1e-6f);                 // -f'
        float fpp = S1 - 3.0f * S2 + 2.0f * S3;           // f''
        float den = fmaf(-f, fpp, 2.0f * aa * aa);        // 2a^2 - f*f''
        dfin = 2.0f * f * aa * frcp(den);                 // final step in ln w
        dfin = fminf(0.5f, fmaxf(-0.5f, dfin));
    }

    // ---- epilogue: i(w*e^d) ~ i*(1+(i-1)*d); P0 = mu*i, P1 = mu - P0 ----
    float* o0 = out + (size_t)b * 2 * NN;
    float* o1 = o0 + NN;
#pragma unroll
    for (int g = 0; g < NG; g++) {
        float4 P0, P1;
        float i0 = i[4 * g + 0], i1 = i[4 * g + 1];
        float i2 = i[4 * g + 2], i3 = i[4 * g + 3];
        // corrected = i + i*(i-1)*d = i*(1 + (i*d - d))
        P0.x = MUF * fmaf(i0, fmaf(i0, dfin, -dfin), i0);
        P0.y = MUF * fmaf(i1, fmaf(i1, dfin, -dfin), i1);
        P0.z = MUF * fmaf(i2, fmaf(i2, dfin, -dfin), i2);
        P0.w = MUF * fmaf(i3, fmaf(i3, dfin, -dfin), i3);
        P1.x = MUF - P0.x;
        P1.y = MUF - P0.y;
        P1.z = MUF - P0.z;
        P1.w = MUF - P0.w;
        __stcs((float4*)(o0) + g * TPB + t, P0);
        __stcs((float4*)(o1) + g * TPB + t, P1);
    }
}

extern "C" void kernel_launch(void* const* d_in, const int* in_sizes, int n_in,
                              void* d_out, int out_size) {
    const float* scores = (const float*)d_in[0];
    float* out = (float*)d_out;

    cudaLaunchAttribute attrs[1];
    attrs[0].id = cudaLaunchAttributeProgrammaticStreamSerialization;
    attrs[0].val.programmaticStreamSerializationAllowed = 1;

    cudaLaunchConfig_t cfg0 = {};
    cfg0.gridDim = dim3(BATCH, 1, 1);
    cfg0.blockDim = dim3(TPB, 1, 1);
    cfg0.stream = 0;
    cfg0.attrs = attrs;
    cfg0.numAttrs = 1;
    cudaLaunchKernelEx(&cfg0, max_kernel, scores);

    cudaLaunchConfig_t cfg1 = cfg0;
    cudaLaunchKernelEx(&cfg1, sinkhorn_kernel, scores, out);
}

// round 15
// speedup vs baseline: 1.0490x; 1.0490x over previous
#include <cuda_runtime.h>

#define BATCH 512
#define NN    4096
#define KK    256
#define EPSF  0.1f
#define MUF   (1.0f / 4096.0f)
#define KF    256.0f
#define L2E   1.4426950408889634f
#define LN15  2.7080502011022101f   // ln(N/K - 1) = ln 15
#define ILAM2 0.3452f               // 1/lambda^2, lambda = 1.70174 (probit blend)

#define TPB   256
#define NG    4                  // float4 quad-groups per thread (16 elems)

__device__ float g_pmax[BATCH];

__device__ __forceinline__ float frcp(float x) {
    float y; asm("rcp.approx.ftz.f32 %0, %1;" : "=f"(y) : "f"(x)); return y;
}
__device__ __forceinline__ float fex2(float x) {
    float y; asm("ex2.approx.ftz.f32 %0, %1;" : "=f"(y) : "f"(x)); return y;
}

// Per-row max of C = max(s^2, (s-1)^2). PDL primary: signals dependents at top.
__global__ void __launch_bounds__(TPB)
max_kernel(const float* __restrict__ scores) {
    asm volatile("griddepcontrol.launch_dependents;" ::: "memory");
    const int b = blockIdx.x;
    const int t = threadIdx.x;
    const float4* s4 = (const float4*)(scores + b * NN);
    float m = 0.0f;
#pragma unroll
    for (int g = 0; g < NG; g++) {
        float4 s = s4[g * TPB + t];
        float a0 = s.x - 1.0f, a1 = s.y - 1.0f, a2 = s.z - 1.0f, a3 = s.w - 1.0f;
        m = fmaxf(m, fmaxf(fmaxf(s.x * s.x, a0 * a0), fmaxf(s.y * s.y, a1 * a1)));
        m = fmaxf(m, fmaxf(fmaxf(s.z * s.z, a2 * a2), fmaxf(s.w * s.w, a3 * a3)));
    }
#pragma unroll
    for (int o = 16; o > 0; o >>= 1)
        m = fmaxf(m, __shfl_xor_sync(0xFFFFFFFFu, m, o));
    __shared__ float red[8];
    if ((t & 31) == 0) red[t >> 5] = m;
    __syncthreads();
    if (t < 32) {
        float x = red[t & 7];
        x = fmaxf(x, __shfl_xor_sync(0xFFFFFFFFu, x, 4));
        x = fmaxf(x, __shfl_xor_sync(0xFFFFFFFFu, x, 2));
        x = fmaxf(x, __shfl_xor_sync(0xFFFFFFFFu, x, 1));
        if (t == 0) g_pmax[b] = x;
    }
}

// One block per row. Solve T(w) = sum_n 1/(1 + w r_n) = K.
// Guess: probit-blended logistic solution (mean-field regime, sigma << lambda):
//   ln w0 = -mu_lnr + ln(15) * sqrt(1 + sigma^2/lambda^2)
// Rounds: Newton (S1,S2), then Halley (S1,S2,S3). Full epilogue recompute.
__global__ void __launch_bounds__(TPB, 4)
sinkhorn_kernel(const float* __restrict__ scores, float* __restrict__ out) {
    const int b = blockIdx.x;
    const int t = threadIdx.x;
    const int wrp = t >> 5;
    const int lane = t & 31;

    __shared__ float cmaxsh;
    __shared__ __align__(16) float2 msum[8];      // per-warp (sum s, sum s^2)
    __shared__ __align__(16) float2 redN[8];      // Newton round: (S1,S2)
    __shared__ __align__(16) float4 redH[8];      // Halley round: (S1,S2,S3,-)

    // ---- score loads + s-moments (independent of the primary kernel) ----
    const float4* s4 = (const float4*)(scores + b * NN);
    float4 s[NG];
#pragma unroll
    for (int g = 0; g < NG; g++) s[g] = s4[g * TPB + t];

    float ss = 0.0f, ss2 = 0.0f;
#pragma unroll
    for (int g = 0; g < NG; g++) {
        ss += (s[g].x + s[g].y) + (s[g].z + s[g].w);
        ss2 = fmaf(s[g].x, s[g].x, fmaf(s[g].y, s[g].y,
              fmaf(s[g].z, s[g].z, fmaf(s[g].w, s[g].w, ss2))));
    }
#pragma unroll
    for (int o = 16; o > 0; o >>= 1) {
        ss  += __shfl_xor_sync(0xFFFFFFFFu, ss, o);
        ss2 += __shfl_xor_sync(0xFFFFFFFFu, ss2, o);
    }
    if (lane == 0) msum[wrp] = make_float2(ss, ss2);

    asm volatile("griddepcontrol.wait;" ::: "memory");

    // ---- cmax: warp 0 alone reduces the 512 row maxes ----
    if (wrp == 0) {
        const float4* p4 = (const float4*)g_pmax;   // 128 float4
        float4 a = p4[lane];
        float4 c = p4[lane + 32];
        float4 d = p4[lane + 64];
        float4 e = p4[lane + 96];
        float m = fmaxf(fmaxf(fmaxf(a.x, a.y), fmaxf(a.z, a.w)),
                        fmaxf(fmaxf(c.x, c.y), fmaxf(c.z, c.w)));
        m = fmaxf(m, fmaxf(fmaxf(fmaxf(d.x, d.y), fmaxf(d.z, d.w)),
                           fmaxf(fmaxf(e.x, e.y), fmaxf(e.z, e.w))));
#pragma unroll
        for (int o = 16; o > 0; o >>= 1)
            m = fmaxf(m, __shfl_xor_sync(0xFFFFFFFFu, m, o));
        if (lane == 0) cmaxsh = m;
    }
    __syncthreads();
    // cmax consumed -> allow next replay's max_kernel (rewrites identical values).
    asm volatile("griddepcontrol.launch_dependents;" ::: "memory");

    const float inv = frcp(cmaxsh * EPSF);     // 1/(cmax*eps)
    const float ca = 2.0f * inv * L2E;         // r = ex2(ca*s + cb)
    const float cb = -inv * L2E;

    // ---- probit-blended initial guess ----
    float w;
    {
        float2 a0 = msum[0], a1 = msum[1], a2 = msum[2], a3 = msum[3];
        float2 a4 = msum[4], a5 = msum[5], a6 = msum[6], a7 = msum[7];
        float S  = ((a0.x + a1.x) + (a2.x + a3.x)) + ((a4.x + a5.x) + (a6.x + a7.x));
        float Q  = ((a0.y + a1.y) + (a2.y + a3.y)) + ((a4.y + a5.y) + (a6.y + a7.y));
        float ms = S * MUF;                         // mean(s)
        float vs = fmaxf(Q * MUF - ms * ms, 0.0f);  // var(s)
        float mu_lnr = (2.0f * ms - 1.0f) * inv;    // mean(ln r)
        float sig2 = 4.0f * vs * inv * inv;         // var(ln r)
        float lnw0 = -mu_lnr + LN15 * sqrtf(fmaf(sig2, ILAM2, 1.0f));
        w = fex2(lnw0 * L2E);
    }

    // ---- r in registers ----
    float r[4 * NG];
#pragma unroll
    for (int g = 0; g < NG; g++) {
        r[4 * g + 0] = fex2(fmaf(ca, s[g].x, cb));
        r[4 * g + 1] = fex2(fmaf(ca, s[g].y, cb));
        r[4 * g + 2] = fex2(fmaf(ca, s[g].z, cb));
        r[4 * g + 3] = fex2(fmaf(ca, s[g].w, cb));
    }

    // ---- round 1: Newton with (S1,S2) payload ----
    {
        float S1 = 0.0f, S2 = 0.0f;
#pragma unroll
        for (int g = 0; g < NG; g++) {
            float d0 = fmaf(w, r[4 * g + 0], 1.0f);
            float d1 = fmaf(w, r[4 * g + 1], 1.0f);
            float d2 = fmaf(w, r[4 * g + 2], 1.0f);
            float d3 = fmaf(w, r[4 * g + 3], 1.0f);
            float d01 = d0 * d1, d23 = d2 * d3;
            float rp = frcp(d01 * d23);
            float i0 = d1 * d23 * rp;
            float i1 = d0 * d23 * rp;
            float i2 = d3 * d01 * rp;
            float i3 = d2 * d01 * rp;
            S1 += (i0 + i1) + (i2 + i3);
            S2 = fmaf(i0, i0, fmaf(i1, i1, fmaf(i2, i2, fmaf(i3, i3, S2))));
        }
#pragma unroll
        for (int o = 16; o > 0; o >>= 1) {
            S1 += __shfl_xor_sync(0xFFFFFFFFu, S1, o);
            S2 += __shfl_xor_sync(0xFFFFFFFFu, S2, o);
        }
        if (lane == 0) redN[wrp] = make_float2(S1, S2);
        __syncthreads();
        {
            float2 v0 = redN[0], v1 = redN[1], v2 = redN[2], v3 = redN[3];
            float2 v4 = redN[4], v5 = redN[5], v6 = redN[6], v7 = redN[7];
            S1 = ((v0.x + v1.x) + (v2.x + v3.x)) + ((v4.x + v5.x) + (v6.x + v7.x));
            S2 = ((v0.y + v1.y) + (v2.y + v3.y)) + ((v4.y + v5.y) + (v6.y + v7.y));
        }
        float f = S1 - KF;
        float aa = fmaxf(S1 - S2, 1e-6f);            // -f' in ln w
        float d = fminf(4.0f, fmaxf(-4.0f, f * frcp(aa)));
        w = w * fex2(d * L2E);
    }

    // ---- round 2: Halley with (S1,S2,S3) ----
    {
        float S1 = 0.0f, S2 = 0.0f, S3 = 0.0f;
#pragma unroll
        for (int g = 0; g < NG; g++) {
            float d0 = fmaf(w, r[4 * g + 0], 1.0f);
            float d1 = fmaf(w, r[4 * g + 1], 1.0f);
            float d2 = fmaf(w, r[4 * g + 2], 1.0f);
            float d3 = fmaf(w, r[4 * g + 3], 1.0f);
            float d01 = d0 * d1, d23 = d2 * d3;
            float rp = frcp(d01 * d23);
            float i0 = d1 * d23 * rp;
            float i1 = d0 * d23 * rp;
            float i2 = d3 * d01 * rp;
            float i3 = d2 * d01 * rp;
            S1 += (i0 + i1) + (i2 + i3);
            float q0 = i0 * i0, q1 = i1 * i1, q2 = i2 * i2, q3 = i3 * i3;
            S2 += (q0 + q1) + (q2 + q3);
            S3 = fmaf(q0, i0, fmaf(q1, i1, fmaf(q2, i2, fmaf(q3, i3, S3))));
        }
#pragma unroll
        for (int o = 16; o > 0; o >>= 1) {
            S1 += __shfl_xor_sync(0xFFFFFFFFu, S1, o);
            S2 += __shfl_xor_sync(0xFFFFFFFFu, S2, o);
            S3 += __shfl_xor_sync(0xFFFFFFFFu, S3, o);
        }
        if (lane == 0) redH[wrp] = make_float4(S1, S2, S3, 0.0f);
        __syncthreads();
        {
            float4 v0 = redH[0], v1 = redH[1], v2 = redH[2], v3 = redH[3];
            float4 v4 = redH[4], v5 = redH[5], v6 = redH[6], v7 = redH[7];
            S1 = ((v0.x + v1.x) + (v2.x + v3.x)) + ((v4.x + v5.x) + (v6.x + v7.x));
            S2 = ((v0.y + v1.y) + (v2.y + v3.y)) + ((v4.y + v5.y) + (v6.y + v7.y));
            S3 = ((v0.z + v1.z) + (v2.z + v3.z)) + ((v4.z + v5.z) + (v6.z + v7.z));
        }
        float f = S1 - KF;
        float aa = fmaxf(S1 - S2, 1e-6f);                 // -f'
        float fpp = S1 - 3.0f * S2 + 2.0f * S3;           // f''
        float den = fmaf(-f, fpp, 2.0f * aa * aa);        // 2a^2 - f*f''
        float d = 2.0f * f * aa * frcp(den);              // Halley step in ln w
        d = fminf(4.0f, fmaxf(-4.0f, d));
        w = w * fex2(d * L2E);
    }

    // ---- epilogue: P0 = mu/(1+w r) grouped-rcp; streaming stores ----
    float* o0 = out + (size_t)b * 2 * NN;
    float* o1 = o0 + NN;
#pragma unroll
    for (int g = 0; g < NG; g++) {
        float d0 = fmaf(w, r[4 * g + 0], 1.0f);
        float d1 = fmaf(w, r[4 * g + 1], 1.0f);
        float d2 = fmaf(w, r[4 * g + 2], 1.0f);
        float d3 = fmaf(w, r[4 * g + 3], 1.0f);
        float d01 = d0 * d1, d23 = d2 * d3;
        float mrp = MUF * frcp(d01 * d23);
        float4 P0, P1;
        P0.x = d1 * d23 * mrp;
        P0.y = d0 * d23 * mrp;
        P0.z = d3 * d01 * mrp;
        P0.w = d2 * d01 * mrp;
        P1.x = MUF - P0.x;
        P1.y = MUF - P0.y;
        P1.z = MUF - P0.z;
        P1.w = MUF - P0.w;
        __stcs((float4*)(o0) + g * TPB + t, P0);
        __stcs((float4*)(o1) + g * TPB + t, P1);
    }
}

extern "C" void kernel_launch(void* const* d_in, const int* in_sizes, int n_in,
                              void* d_out, int out_size) {
    const float* scores = (const float*)d_in[0];
    float* out = (float*)d_out;

    cudaLaunchAttribute attrs[1];
    attrs[0].id = cudaLaunchAttributeProgrammaticStreamSerialization;
    attrs[0].val.programmaticStreamSerializationAllowed = 1;

    cudaLaunchConfig_t cfg0 = {};
    cfg0.gridDim = dim3(BATCH, 1, 1);
    cfg0.blockDim = dim3(TPB, 1, 1);
    cfg0.stream = 0;
    cfg0.attrs = attrs;
    cfg0.numAttrs = 1;
    cudaLaunchKernelEx(&cfg0, max_kernel, scores);

    cudaLaunchConfig_t cfg1 = cfg0;
    cudaLaunchKernelEx(&cfg1, sinkhorn_kernel, scores, out);
}